// round 12
// baseline (speedup 1.0000x reference)
#include <cuda_runtime.h>
#include <math_constants.h>

// ---------------- problem constants ----------------
#define BATCH 4
#define HW    16384          // 128*128
#define THR   0.1f
#define TS    2048           // shared column tile == column chunk
#define RPT   4              // rows per thread in dist kernel
#define DBLK  256            // threads per dist block -> 1024 rows/block
#define ROWCHUNK (DBLK*RPT)  // 1024
#define NROW  (HW/ROWCHUNK)  // 16 row chunks
#define NCOL  (HW/TS)        // 8  col chunks
#define NSLICE 8             // compact slices

// ---------------- device scratch (no allocs allowed; zero-initialized) ------
__device__ float g_px[2][BATCH][HW];
__device__ float g_py[2][BATCH][HW];
__device__ float g_pn[2][BATCH][HW];
__device__ int   g_cnt[2][BATCH];          // statically 0; reset by last block
__device__ unsigned int g_minbuf[8][HW];   // [dir*4+b][row], ordered-uint
__device__ float g_dirsum[8];
__device__ int   g_tick[8];                // per-z block tickets
__device__ int   g_done;                   // z-completion counter

// ---------------- helpers ----------------
__device__ __forceinline__ unsigned fp_ord(float f) {
    unsigned u = __float_as_uint(f);
    return (u & 0x80000000u) ? ~u : (u | 0x80000000u);
}
__device__ __forceinline__ float fp_unord(unsigned u) {
    u = (u & 0x80000000u) ? (u & 0x7fffffffu) : ~u;
    return __uint_as_float(u);
}

// ---------------- kernel 1: compaction + minbuf init ----------------
// grid (NSLICE, 8 set*4+b), 256 threads; order within compacted array is free
__global__ void k_compact(const float* __restrict__ b1, const float* __restrict__ b2) {
    int bs = blockIdx.y;
    int set = bs >> 2, b = bs & 3;
    const float* src = (set == 0 ? b1 : b2) + b * HW;
    int begin = blockIdx.x * (HW / NSLICE);        // 2048-element slice

    // init min buffer slice (z == bs: rows of dir==set)
    {
        uint4* mb = (uint4*)&g_minbuf[bs][begin];
        uint4 v = make_uint4(0xFFFFFFFFu, 0xFFFFFFFFu, 0xFFFFFFFFu, 0xFFFFFFFFu);
        for (int i = threadIdx.x; i < (HW / NSLICE) / 4; i += 256) mb[i] = v;
    }

    int lane = threadIdx.x & 31;
    for (int k = 0; k < (HW / NSLICE) / 256; k++) { // uniform trip count: ballot safe
        int i = begin + k * 256 + threadIdx.x;
        float v = src[i];
        float w = v - THR;
        bool act = (w > 0.0f);
        unsigned mask = __ballot_sync(0xffffffffu, act);
        int c = __popc(mask);
        int base = 0;
        if (lane == 0 && c) base = atomicAdd(&g_cnt[set][b], c);
        base = __shfl_sync(0xffffffffu, base, 0);
        if (act) {
            int pos = base + __popc(mask & ((1u << lane) - 1u));
            float y = (float)(i >> 7);
            float x = (float)(i & 127);
            float px = y * w, py = x * w;
            g_px[set][b][pos] = px;
            g_py[set][b][pos] = py;
            g_pn[set][b][pos] = fmaf(px, px, py * py);
        }
    }
}

// ---------------- kernel 2: pairwise min + fused finalize ----------------
// grid (NROW, NCOL, 8): x=row chunk (1024), y=col chunk (2048), z=dir*4+b
__global__ void __launch_bounds__(DBLK, 4) k_dist(float* __restrict__ out) {
    int z = blockIdx.z;
    int dir = z >> 2, b = z & 3;
    int n1 = g_cnt[dir][b];          // rows come from set==dir
    int n2 = g_cnt[dir ^ 1][b];      // columns from the other set

    int rowBase = blockIdx.x * ROWCHUNK;
    int colBase = blockIdx.y * TS;
    int t = threadIdx.x;
    const float FINF = CUDART_INF_F;

    __shared__ __align__(16) float sqx[TS];
    __shared__ __align__(16) float sqy[TS];
    __shared__ __align__(16) float sqn[TS];
    __shared__ float ws[8];
    __shared__ int s_last;

    if (rowBase < n1 && colBase < n2) {
        const float* qx = g_px[dir ^ 1][b];
        const float* qy = g_py[dir ^ 1][b];
        const float* qn = g_pn[dir ^ 1][b];

        // unconditional vector tile load; force qn=INF beyond n2 so padded
        // columns self-exclude (stale qx/qy finite -> result +INF, never NaN)
#pragma unroll
        for (int p = 0; p < TS / (DBLK * 4); p++) {     // 2 passes
            int v4 = p * DBLK + t;
            float4 vx = ((const float4*)(qx + colBase))[v4];
            float4 vy = ((const float4*)(qy + colBase))[v4];
            float4 vn = ((const float4*)(qn + colBase))[v4];
            int cb = colBase + v4 * 4;
            vn.x = (cb + 0 < n2) ? vn.x : FINF;
            vn.y = (cb + 1 < n2) ? vn.y : FINF;
            vn.z = (cb + 2 < n2) ? vn.z : FINF;
            vn.w = (cb + 3 < n2) ? vn.w : FINF;
            ((float4*)sqx)[v4] = vx;
            ((float4*)sqy)[v4] = vy;
            ((float4*)sqn)[v4] = vn;
        }

        float a[RPT], bb[RPT], mnA[RPT], mnB[RPT];
#pragma unroll
        for (int r = 0; r < RPT; r++) {
            int row = rowBase + t + r * DBLK;
            float px = 0.0f, py = 0.0f;
            if (row < n1) { px = g_px[dir][b][row]; py = g_py[dir][b][row]; }
            a[r]  = -2.0f * px;
            bb[r] = -2.0f * py;
            mnA[r] = FINF;
            mnB[r] = FINF;
        }

        __syncthreads();

#pragma unroll 2
        for (int j = 0; j < TS; j += 4) {
            float4 X = *(const float4*)&sqx[j];
            float4 Y = *(const float4*)&sqy[j];
            float4 N = *(const float4*)&sqn[j];
#pragma unroll
            for (int r = 0; r < RPT; r++) {
                float v0 = fmaf(a[r], X.x, fmaf(bb[r], Y.x, N.x));
                float v1 = fmaf(a[r], X.y, fmaf(bb[r], Y.y, N.y));
                float v2 = fmaf(a[r], X.z, fmaf(bb[r], Y.z, N.z));
                float v3 = fmaf(a[r], X.w, fmaf(bb[r], Y.w, N.w));
                mnA[r] = fminf(mnA[r], fminf(v0, v2));
                mnB[r] = fminf(mnB[r], fminf(v1, v3));
            }
        }

#pragma unroll
        for (int r = 0; r < RPT; r++) {
            int row = rowBase + t + r * DBLK;
            if (row < n1) atomicMin(&g_minbuf[z][row], fp_ord(fminf(mnA[r], mnB[r])));
        }
    }

    // ---- ticket: last block of this z reduces minbuf -> g_dirsum[z] ----
    __syncthreads();
    __threadfence();
    if (t == 0) {
        int tk = atomicAdd(&g_tick[z], 1);
        s_last = (tk == NROW * NCOL - 1);
    }
    __syncthreads();
    if (!s_last) return;
    __threadfence();

    {
        const float* pn = g_pn[dir][b];
        const unsigned* mb = g_minbuf[z];
        float s = 0.0f;
        for (int i = t; i < n1; i += DBLK) {
            float d2 = pn[i] + fp_unord(mb[i]);
            s += sqrtf(fmaxf(d2, 1e-12f));
        }
        for (int o = 16; o; o >>= 1) s += __shfl_down_sync(0xffffffffu, s, o);
        if ((t & 31) == 0) ws[t >> 5] = s;
        __syncthreads();
        if (t == 0) {
            float v = 0.0f;
#pragma unroll
            for (int w = 0; w < DBLK / 32; w++) v += ws[w];
            g_dirsum[z] = v / (float)max(n1, 1);
            __threadfence();
            int dz = atomicAdd(&g_done, 1);
            s_last = (dz == 7);
        }
        __syncthreads();
        if (!s_last) return;
        __threadfence();

        // very last block: write outputs + reset counters for next replay
        if (t < BATCH) {
            int c1 = g_cnt[0][t], c2 = g_cnt[1][t];
            volatile float* dsum = g_dirsum;
            float r = dsum[t] + dsum[4 + t];
            out[t] = (c1 > 0 && c2 > 0) ? r : 1.0e6f;
        }
        __syncthreads();
        if (t < 8)  g_tick[t] = 0;
        if (t < 8)  ((int*)g_cnt)[t & 7] = 0;
        if (t == 0) g_done = 0;
    }
}

// ---------------- launch ----------------
extern "C" void kernel_launch(void* const* d_in, const int* in_sizes, int n_in,
                              void* d_out, int out_size) {
    const float* b1 = (const float*)d_in[0];
    const float* b2 = (const float*)d_in[1];
    float* out = (float*)d_out;

    {
        dim3 g(NSLICE, 8);
        k_compact<<<g, 256>>>(b1, b2);
    }
    {
        dim3 g(NROW, NCOL, 8);   // (16, 8, 8)
        k_dist<<<g, DBLK>>>(out);
    }
}

// round 13
// speedup vs baseline: 1.0030x; 1.0030x over previous
#include <cuda_runtime.h>
#include <math_constants.h>

// ---------------- problem constants ----------------
#define BATCH 4
#define HW    16384          // 128*128
#define THR   0.1f
#define TS    2048           // shared column tile == column chunk
#define RPT   4              // rows per thread in dist kernel
#define DBLK  256            // threads per dist block -> 1024 rows/block
#define ROWCHUNK (DBLK*RPT)  // 1024
#define NROW  (HW/ROWCHUNK)  // 16 row chunks
#define NCOL  (HW/TS)        // 8  col chunks
#define NSLICE 8             // compact slices

// ---------------- device scratch (no allocs allowed; zero-initialized) ------
__device__ float g_px[2][BATCH][HW];
__device__ float g_py[2][BATCH][HW];
__device__ float g_pn[2][BATCH][HW];
__device__ int   g_cnt[2][BATCH];          // statically 0; reset by last block
__device__ unsigned int g_minbuf[8][HW];   // [dir*4+b][row], ordered-uint
__device__ float g_dirsum[8];
__device__ int   g_tick[8];                // per-z block tickets
__device__ int   g_done;                   // z-completion counter

// ---------------- helpers ----------------
__device__ __forceinline__ unsigned fp_ord(float f) {
    unsigned u = __float_as_uint(f);
    return (u & 0x80000000u) ? ~u : (u | 0x80000000u);
}
__device__ __forceinline__ float fp_unord(unsigned u) {
    u = (u & 0x80000000u) ? (u & 0x7fffffffu) : ~u;
    return __uint_as_float(u);
}

// ---------------- kernel 1: compaction + minbuf init ----------------
// grid (NSLICE, 8 set*4+b), 256 threads; order within compacted array is free
__global__ void k_compact(const float* __restrict__ b1, const float* __restrict__ b2) {
    int bs = blockIdx.y;
    int set = bs >> 2, b = bs & 3;
    const float* src = (set == 0 ? b1 : b2) + b * HW;
    int begin = blockIdx.x * (HW / NSLICE);        // 2048-element slice

    // init min buffer slice (z == bs: rows of dir==set)
    {
        uint4* mb = (uint4*)&g_minbuf[bs][begin];
        uint4 v = make_uint4(0xFFFFFFFFu, 0xFFFFFFFFu, 0xFFFFFFFFu, 0xFFFFFFFFu);
        for (int i = threadIdx.x; i < (HW / NSLICE) / 4; i += 256) mb[i] = v;
    }

    int lane = threadIdx.x & 31;
    for (int k = 0; k < (HW / NSLICE) / 256; k++) { // uniform trip count: ballot safe
        int i = begin + k * 256 + threadIdx.x;
        float v = src[i];
        float w = v - THR;
        bool act = (w > 0.0f);
        unsigned mask = __ballot_sync(0xffffffffu, act);
        int c = __popc(mask);
        int base = 0;
        if (lane == 0 && c) base = atomicAdd(&g_cnt[set][b], c);
        base = __shfl_sync(0xffffffffu, base, 0);
        if (act) {
            int pos = base + __popc(mask & ((1u << lane) - 1u));
            float y = (float)(i >> 7);
            float x = (float)(i & 127);
            float px = y * w, py = x * w;
            g_px[set][b][pos] = px;
            g_py[set][b][pos] = py;
            g_pn[set][b][pos] = fmaf(px, px, py * py);
        }
    }
}

// ---------------- kernel 2: pairwise min + fused finalize ----------------
// grid (NROW, NCOL, 8): x=row chunk (1024), y=col chunk (2048), z=dir*4+b
__global__ void __launch_bounds__(DBLK, 4) k_dist(float* __restrict__ out) {
    int z = blockIdx.z;
    int dir = z >> 2, b = z & 3;
    int n1 = g_cnt[dir][b];          // rows come from set==dir
    int n2 = g_cnt[dir ^ 1][b];      // columns from the other set

    int rowBase = blockIdx.x * ROWCHUNK;
    int colBase = blockIdx.y * TS;
    int t = threadIdx.x;
    const float FINF = CUDART_INF_F;

    __shared__ __align__(16) float sqx[TS];
    __shared__ __align__(16) float sqy[TS];
    __shared__ __align__(16) float sqn[TS];
    __shared__ float ws[8];
    __shared__ int s_last;

    if (rowBase < n1 && colBase < n2) {
        const float* qx = g_px[dir ^ 1][b];
        const float* qy = g_py[dir ^ 1][b];
        const float* qn = g_pn[dir ^ 1][b];

        // unconditional vector tile load; force qn=INF beyond n2 so padded
        // columns self-exclude (stale qx/qy finite -> result +INF, never NaN)
#pragma unroll
        for (int p = 0; p < TS / (DBLK * 4); p++) {     // 2 passes
            int v4 = p * DBLK + t;
            float4 vx = ((const float4*)(qx + colBase))[v4];
            float4 vy = ((const float4*)(qy + colBase))[v4];
            float4 vn = ((const float4*)(qn + colBase))[v4];
            int cb = colBase + v4 * 4;
            vn.x = (cb + 0 < n2) ? vn.x : FINF;
            vn.y = (cb + 1 < n2) ? vn.y : FINF;
            vn.z = (cb + 2 < n2) ? vn.z : FINF;
            vn.w = (cb + 3 < n2) ? vn.w : FINF;
            ((float4*)sqx)[v4] = vx;
            ((float4*)sqy)[v4] = vy;
            ((float4*)sqn)[v4] = vn;
        }

        float a[RPT], bb[RPT], mnA[RPT], mnB[RPT];
#pragma unroll
        for (int r = 0; r < RPT; r++) {
            int row = rowBase + t + r * DBLK;
            float px = 0.0f, py = 0.0f;
            if (row < n1) { px = g_px[dir][b][row]; py = g_py[dir][b][row]; }
            a[r]  = -2.0f * px;
            bb[r] = -2.0f * py;
            mnA[r] = FINF;
            mnB[r] = FINF;
        }

        __syncthreads();

#pragma unroll 2
        for (int j = 0; j < TS; j += 4) {
            float4 X = *(const float4*)&sqx[j];
            float4 Y = *(const float4*)&sqy[j];
            float4 N = *(const float4*)&sqn[j];
#pragma unroll
            for (int r = 0; r < RPT; r++) {
                float v0 = fmaf(a[r], X.x, fmaf(bb[r], Y.x, N.x));
                float v1 = fmaf(a[r], X.y, fmaf(bb[r], Y.y, N.y));
                float v2 = fmaf(a[r], X.z, fmaf(bb[r], Y.z, N.z));
                float v3 = fmaf(a[r], X.w, fmaf(bb[r], Y.w, N.w));
                mnA[r] = fminf(mnA[r], fminf(v0, v2));
                mnB[r] = fminf(mnB[r], fminf(v1, v3));
            }
        }

#pragma unroll
        for (int r = 0; r < RPT; r++) {
            int row = rowBase + t + r * DBLK;
            if (row < n1) atomicMin(&g_minbuf[z][row], fp_ord(fminf(mnA[r], mnB[r])));
        }
    }

    // ---- ticket: last block of this z reduces minbuf -> g_dirsum[z] ----
    __syncthreads();
    __threadfence();
    if (t == 0) {
        int tk = atomicAdd(&g_tick[z], 1);
        s_last = (tk == NROW * NCOL - 1);
    }
    __syncthreads();
    if (!s_last) return;
    __threadfence();

    {
        const float* pn = g_pn[dir][b];
        const unsigned* mb = g_minbuf[z];
        float s = 0.0f;
        for (int i = t; i < n1; i += DBLK) {
            float d2 = pn[i] + fp_unord(mb[i]);
            s += sqrtf(fmaxf(d2, 1e-12f));
        }
        for (int o = 16; o; o >>= 1) s += __shfl_down_sync(0xffffffffu, s, o);
        if ((t & 31) == 0) ws[t >> 5] = s;
        __syncthreads();
        if (t == 0) {
            float v = 0.0f;
#pragma unroll
            for (int w = 0; w < DBLK / 32; w++) v += ws[w];
            g_dirsum[z] = v / (float)max(n1, 1);
            __threadfence();
            int dz = atomicAdd(&g_done, 1);
            s_last = (dz == 7);
        }
        __syncthreads();
        if (!s_last) return;
        __threadfence();

        // very last block: write outputs + reset counters for next replay
        if (t < BATCH) {
            int c1 = g_cnt[0][t], c2 = g_cnt[1][t];
            volatile float* dsum = g_dirsum;
            float r = dsum[t] + dsum[4 + t];
            out[t] = (c1 > 0 && c2 > 0) ? r : 1.0e6f;
        }
        __syncthreads();
        if (t < 8)  g_tick[t] = 0;
        if (t < 8)  ((int*)g_cnt)[t & 7] = 0;
        if (t == 0) g_done = 0;
    }
}

// ---------------- launch ----------------
extern "C" void kernel_launch(void* const* d_in, const int* in_sizes, int n_in,
                              void* d_out, int out_size) {
    const float* b1 = (const float*)d_in[0];
    const float* b2 = (const float*)d_in[1];
    float* out = (float*)d_out;

    {
        dim3 g(NSLICE, 8);
        k_compact<<<g, 256>>>(b1, b2);
    }
    {
        dim3 g(NROW, NCOL, 8);   // (16, 8, 8)
        k_dist<<<g, DBLK>>>(out);
    }
}